// round 3
// baseline (speedup 1.0000x reference)
#include <cuda_runtime.h>
#include <cuda_bf16.h>
#include <cstdint>

// ============================================================================
// NeuralODE on GB300 via portable mma.sync (compute_103-safe; no tcgen05).
// 128 CTAs x 32 batch rows, persistent over all steps.
// Per step (per CTA): H1 = tanh(X@W1+b1); H2 = tanh(H1@W2+b2); F = H2@W3;
//   x += (F + b3)*dt_scale*DT; write trajectory row.
// All weights (bf16, transposed, padded strides -> ldmatrix conflict-free)
// and activations live in shared memory. fp32 state x lives in registers.
// ============================================================================

#define STATE     64
#define HID       256
#define BATCHN    4096
#define MROWS     32
#define NCTAS     (BATCHN / MROWS)   // 128
#define NTHREADS  256

// ---- smem layout (byte offsets; all bases 16B aligned) ----
// row strides chosen so (stride/16) is odd -> ldmatrix conflict-free
#define W2_STR 528   // 256 bf16 + 8 pad
#define W1_STR 144   //  64 bf16 + 8 pad
#define W3_STR 528
#define XB_STR 144
#define H_STR  528
#define F_STRF 68    // floats per row (272 B)

#define W2_OFF 0u          // 256 x 528 = 135168
#define W1_OFF 135168u     // 256 x 144 =  36864
#define W3_OFF 172032u     //  64 x 528 =  33792
#define XB_OFF 205824u     //  32 x 144 =   4608
#define H_OFF  210432u     //  32 x 528 =  16896  (aliased as F fp32 buffer)
#define F_OFF  210432u
#define B1_OFF 227328u
#define B2_OFF 228352u
#define B3_OFF 229376u
#define SMEM_BYTES 229632u

// ============================================================================
// helpers
// ============================================================================
static __device__ __forceinline__ uint32_t smem_u32(const void* p) {
    uint32_t a;
    asm("{ .reg .u64 t; cvta.to.shared.u64 t, %1; cvt.u32.u64 %0, t; }"
        : "=r"(a) : "l"(p));
    return a;
}

static __device__ __forceinline__ float fast_tanh(float x) {
    float y;
    asm("tanh.approx.f32 %0, %1;" : "=f"(y) : "f"(x));
    return y;
}

static __device__ __forceinline__ uint32_t pack_bf16x2(float lo, float hi) {
    uint32_t p;
    asm("cvt.rn.bf16x2.f32 %0, %1, %2;" : "=r"(p) : "f"(hi), "f"(lo));
    return p;
}

static __device__ __forceinline__ void ldm_x4(uint32_t* r, uint32_t addr) {
    asm volatile("ldmatrix.sync.aligned.m8n8.x4.shared.b16 {%0,%1,%2,%3}, [%4];"
                 : "=r"(r[0]), "=r"(r[1]), "=r"(r[2]), "=r"(r[3]) : "r"(addr));
}

static __device__ __forceinline__ void mma_bf16(float* d, const uint32_t* a,
                                                const uint32_t* b) {
    asm volatile(
        "mma.sync.aligned.m16n8k16.row.col.f32.bf16.bf16.f32 "
        "{%0,%1,%2,%3}, {%4,%5,%6,%7}, {%8,%9}, {%0,%1,%2,%3};"
        : "+f"(d[0]), "+f"(d[1]), "+f"(d[2]), "+f"(d[3])
        : "r"(a[0]), "r"(a[1]), "r"(a[2]), "r"(a[3]), "r"(b[0]), "r"(b[1]));
}

// ============================================================================
// One tanh-GEMM stage: H = tanh( A[32xK] @ B^T + bias ), B stored [256n x K]
// with row stride B_STR bytes. Warp w owns n-cols [32w,32w+32).
// SYNC_BEFORE_WRITE: needed when destination aliases the A source (stage2).
// ============================================================================
template <int KSTEPS, int B_STR, bool SYNC_BEFORE_WRITE>
static __device__ __forceinline__ void gemm_tanh(
    char* smem, uint32_t sb,
    uint32_t a_off, uint32_t a_str,
    uint32_t b_off, const float* __restrict__ bias,
    int wid, int lane)
{
    const int nb = wid * 32;
    float acc[2][4][4];
    #pragma unroll
    for (int i = 0; i < 2; i++)
        #pragma unroll
        for (int j = 0; j < 4; j++)
            #pragma unroll
            for (int c = 0; c < 4; c++) acc[i][j][c] = 0.f;

    const uint32_t a_base = sb + a_off + (uint32_t)(lane & 15) * a_str
                          + (uint32_t)(lane >> 4) * 16u;        // + 8 elems * 2B
    const uint32_t q = (uint32_t)(lane >> 3), r = (uint32_t)(lane & 7);
    const uint32_t b_base = sb + b_off
                          + (uint32_t)(nb + (int)((q >> 1) * 8) + (int)r) * (uint32_t)B_STR
                          + (q & 1) * 16u;

    #pragma unroll
    for (int ks = 0; ks < KSTEPS; ks++) {
        const uint32_t kb = (uint32_t)ks * 32u;   // 16 elems * 2B
        uint32_t a0[4], a1[4], b01[4], b23[4];
        ldm_x4(a0, a_base + kb);
        ldm_x4(a1, a_base + 16u * a_str + kb);
        ldm_x4(b01, b_base + kb);
        ldm_x4(b23, b_base + 16u * (uint32_t)B_STR + kb);
        mma_bf16(acc[0][0], a0, b01 + 0);
        mma_bf16(acc[0][1], a0, b01 + 2);
        mma_bf16(acc[0][2], a0, b23 + 0);
        mma_bf16(acc[0][3], a0, b23 + 2);
        mma_bf16(acc[1][0], a1, b01 + 0);
        mma_bf16(acc[1][1], a1, b01 + 2);
        mma_bf16(acc[1][2], a1, b23 + 0);
        mma_bf16(acc[1][3], a1, b23 + 2);
    }

    if (SYNC_BEFORE_WRITE) __syncthreads();

    #pragma unroll
    for (int mt = 0; mt < 2; mt++) {
        const int row = mt * 16 + (lane >> 2);
        #pragma unroll
        for (int nt = 0; nt < 4; nt++) {
            const int col = nb + nt * 8 + 2 * (lane & 3);
            const float bb0 = bias[col], bb1 = bias[col + 1];
            float v0 = fast_tanh(acc[mt][nt][0] + bb0);
            float v1 = fast_tanh(acc[mt][nt][1] + bb1);
            float v2 = fast_tanh(acc[mt][nt][2] + bb0);
            float v3 = fast_tanh(acc[mt][nt][3] + bb1);
            *reinterpret_cast<uint32_t*>(smem + H_OFF + (uint32_t)row * H_STR
                                         + (uint32_t)col * 2u) = pack_bf16x2(v0, v1);
            *reinterpret_cast<uint32_t*>(smem + H_OFF + (uint32_t)(row + 8) * H_STR
                                         + (uint32_t)col * 2u) = pack_bf16x2(v2, v3);
        }
    }
}

// ============================================================================
// Kernel
// ============================================================================
__global__ void __launch_bounds__(NTHREADS, 1)
neural_ode_kernel(const float* __restrict__ x0, const float* __restrict__ W1,
                  const float* __restrict__ b1, const float* __restrict__ W2,
                  const float* __restrict__ b2, const float* __restrict__ W3,
                  const float* __restrict__ b3, const float* __restrict__ dts,
                  float* __restrict__ out, int T)
{
    extern __shared__ char smem[];
    const uint32_t sb = smem_u32(smem);
    const int tid = threadIdx.x;
    const int wid = tid >> 5;
    const int lane = tid & 31;

    // ---- one-time: bf16 transposed weights into padded smem ----
    for (int i = tid; i < STATE * HID; i += NTHREADS) {          // W1 [64k][256n]
        int k = i >> 8, n = i & 255;
        *reinterpret_cast<__nv_bfloat16*>(smem + W1_OFF + (uint32_t)n * W1_STR
                                          + (uint32_t)k * 2u) = __float2bfloat16(W1[i]);
    }
    for (int i = tid; i < HID * HID; i += NTHREADS) {            // W2 [256k][256n]
        int k = i >> 8, n = i & 255;
        *reinterpret_cast<__nv_bfloat16*>(smem + W2_OFF + (uint32_t)n * W2_STR
                                          + (uint32_t)k * 2u) = __float2bfloat16(W2[i]);
    }
    for (int i = tid; i < HID * STATE; i += NTHREADS) {          // W3 [256k][64n]
        int k = i >> 6, n = i & 63;
        *reinterpret_cast<__nv_bfloat16*>(smem + W3_OFF + (uint32_t)n * W3_STR
                                          + (uint32_t)k * 2u) = __float2bfloat16(W3[i]);
    }
    float* b1s = reinterpret_cast<float*>(smem + B1_OFF);
    float* b2s = reinterpret_cast<float*>(smem + B2_OFF);
    float* b3s = reinterpret_cast<float*>(smem + B3_OFF);
    for (int i = tid; i < HID; i += NTHREADS) { b1s[i] = b1[i]; b2s[i] = b2[i]; }
    for (int i = tid; i < STATE; i += NTHREADS) b3s[i] = b3[i];

    const float dtdt = dts[0] * 0.01f;
    const int nsteps = T - 1;

    // ---- fp32 state ownership: thread t owns row (t>>3), cols (t&7)*8 .. +7 ----
    const int orow = tid >> 3;
    const int ocg = tid & 7;
    const int grow = blockIdx.x * MROWS + orow;
    float xr[8];
    {
        const float4* xp = reinterpret_cast<const float4*>(
            x0 + (size_t)grow * STATE + ocg * 8);
        float4* op = reinterpret_cast<float4*>(
            out + (size_t)grow * T * STATE + ocg * 8);
        float4 v0 = xp[0], v1 = xp[1];
        xr[0] = v0.x; xr[1] = v0.y; xr[2] = v0.z; xr[3] = v0.w;
        xr[4] = v1.x; xr[5] = v1.y; xr[6] = v1.z; xr[7] = v1.w;
        op[0] = v0; op[1] = v1;                       // trajectory t=0
        #pragma unroll
        for (int j = 0; j < 4; j++)
            *reinterpret_cast<uint32_t*>(smem + XB_OFF + (uint32_t)orow * XB_STR
                + (uint32_t)(ocg * 8 + 2 * j) * 2u) = pack_bf16x2(xr[2 * j], xr[2 * j + 1]);
    }
    __syncthreads();

    for (int s = 0; s < nsteps; s++) {
        // stage 1: H1 = tanh(X @ W1 + b1)   (K=64, B stride 144)
        gemm_tanh<4, W1_STR, false>(smem, sb, XB_OFF, XB_STR, W1_OFF, b1s, wid, lane);
        __syncthreads();
        // stage 2: H2 = tanh(H1 @ W2 + b2)  (K=256, B stride 528, dest aliases src)
        gemm_tanh<16, W2_STR, true>(smem, sb, H_OFF, H_STR, W2_OFF, b2s, wid, lane);
        __syncthreads();

        // stage 3: F = H2 @ W3   (32 x 64, K=256). Warp w: n-tile w, both m-tiles.
        {
            float f3[2][4];
            #pragma unroll
            for (int i = 0; i < 2; i++)
                #pragma unroll
                for (int c = 0; c < 4; c++) f3[i][c] = 0.f;

            const uint32_t a_base = sb + H_OFF + (uint32_t)(lane & 15) * H_STR
                                  + (uint32_t)(lane >> 4) * 16u;
            const uint32_t q = (uint32_t)(lane >> 3), r = (uint32_t)(lane & 7);
            const uint32_t b_base = sb + W3_OFF
                                  + (uint32_t)(wid * 8 + (int)r) * W3_STR + q * 16u;
            uint32_t bq[4];
            #pragma unroll
            for (int ks = 0; ks < 16; ks++) {
                const uint32_t kb = (uint32_t)ks * 32u;
                uint32_t a0[4], a1[4];
                ldm_x4(a0, a_base + kb);
                ldm_x4(a1, a_base + 16u * H_STR + kb);
                if ((ks & 1) == 0) ldm_x4(bq, b_base + (uint32_t)(ks >> 1) * 64u);
                const uint32_t* bp = (ks & 1) ? (bq + 2) : bq;
                mma_bf16(f3[0], a0, bp);
                mma_bf16(f3[1], a1, bp);
            }
            __syncthreads();   // all H2 reads complete before F overwrites the buffer
            float* F = reinterpret_cast<float*>(smem + F_OFF);
            const int col = wid * 8 + 2 * (lane & 3);
            #pragma unroll
            for (int mt = 0; mt < 2; mt++) {
                const int row = mt * 16 + (lane >> 2);
                F[(uint32_t)row * F_STRF + col]           = f3[mt][0];
                F[(uint32_t)row * F_STRF + col + 1]       = f3[mt][1];
                F[(uint32_t)(row + 8) * F_STRF + col]     = f3[mt][2];
                F[(uint32_t)(row + 8) * F_STRF + col + 1] = f3[mt][3];
            }
        }
        __syncthreads();

        // Euler update + trajectory write + next-step X (bf16)
        {
            const float* F = reinterpret_cast<const float*>(smem + F_OFF);
            #pragma unroll
            for (int j = 0; j < 8; j++) {
                float f = F[(uint32_t)orow * F_STRF + ocg * 8 + j] + b3s[ocg * 8 + j];
                xr[j] = fmaf(f, dtdt, xr[j]);
            }
            float4* op = reinterpret_cast<float4*>(
                out + ((size_t)grow * T + (size_t)(s + 1)) * STATE + ocg * 8);
            op[0] = make_float4(xr[0], xr[1], xr[2], xr[3]);
            op[1] = make_float4(xr[4], xr[5], xr[6], xr[7]);
            #pragma unroll
            for (int j = 0; j < 4; j++)
                *reinterpret_cast<uint32_t*>(smem + XB_OFF + (uint32_t)orow * XB_STR
                    + (uint32_t)(ocg * 8 + 2 * j) * 2u) = pack_bf16x2(xr[2 * j], xr[2 * j + 1]);
        }
        __syncthreads();
    }
}

// ============================================================================
// Launch
// ============================================================================
extern "C" void kernel_launch(void* const* d_in, const int* in_sizes, int n_in,
                              void* d_out, int out_size) {
    const float* x0  = (const float*)d_in[0];
    const float* W1  = (const float*)d_in[1];
    const float* b1  = (const float*)d_in[2];
    const float* W2  = (const float*)d_in[3];
    const float* b2  = (const float*)d_in[4];
    const float* W3  = (const float*)d_in[5];
    const float* b3  = (const float*)d_in[6];
    const float* dts = (const float*)d_in[7];
    float* out = (float*)d_out;

    const int T = out_size / (BATCHN * STATE);   // steps + 1

    cudaFuncSetAttribute(neural_ode_kernel,
                         cudaFuncAttributeMaxDynamicSharedMemorySize, SMEM_BYTES);
    neural_ode_kernel<<<NCTAS, NTHREADS, SMEM_BYTES>>>(
        x0, W1, b1, W2, b2, W3, b3, dts, out, T);
}

// round 5
// speedup vs baseline: 1.1113x; 1.1113x over previous
#include <cuda_runtime.h>
#include <cuda_bf16.h>
#include <cstdint>

// ============================================================================
// NeuralODE, persistent mma.sync kernel (compute_103-safe), round 4.
// 128 CTAs x 32 rows. Per step: H1=tanh(X@W1+b1); H2=tanh(H1@W2+b2);
// F=H2@W3 (W3 B-frags preloaded in regs); x += (F+b3)*dt; x stays in
// D-fragment registers; 3 __syncthreads per step; H double-buffered.
// ============================================================================

#define STATE     64
#define HID       256
#define BATCHN    4096
#define MROWS     32
#define NCTAS     (BATCHN / MROWS)   // 128
#define NTHREADS  256

// ---- smem layout; (stride/16) odd -> ldmatrix conflict-free ----
#define W2_STR 528
#define W1_STR 144
#define W3_STR 528
#define XB_STR 144
#define H_STR  528

#define W2_OFF 0u          // 256 x 528 = 135168
#define W1_OFF 135168u     // 256 x 144 =  36864
#define XB_OFF 172032u     //  32 x 144 =   4608
#define H1_OFF 176640u     //  32 x 528 =  16896
#define H2_OFF 193536u     //  32 x 528 =  16896   (W3 staged over H1+H2 pre-loop)
#define B1_OFF 210432u
#define B2_OFF 211456u
#define B3_OFF 212480u
#define SMEM_BYTES 212736u

// ============================================================================
// helpers
// ============================================================================
static __device__ __forceinline__ uint32_t smem_u32(const void* p) {
    uint32_t a;
    asm("{ .reg .u64 t; cvta.to.shared.u64 t, %1; cvt.u32.u64 %0, t; }"
        : "=r"(a) : "l"(p));
    return a;
}

static __device__ __forceinline__ float fast_tanh(float x) {
    float y;
    asm("tanh.approx.f32 %0, %1;" : "=f"(y) : "f"(x));
    return y;
}

static __device__ __forceinline__ uint32_t pack_bf16x2(float lo, float hi) {
    uint32_t p;
    asm("cvt.rn.bf16x2.f32 %0, %1, %2;" : "=r"(p) : "f"(hi), "f"(lo));
    return p;
}

static __device__ __forceinline__ void ldm_x4(uint32_t* r, uint32_t addr) {
    asm volatile("ldmatrix.sync.aligned.m8n8.x4.shared.b16 {%0,%1,%2,%3}, [%4];"
                 : "=r"(r[0]), "=r"(r[1]), "=r"(r[2]), "=r"(r[3]) : "r"(addr));
}

static __device__ __forceinline__ void mma_bf16(float* d, const uint32_t* a,
                                                const uint32_t* b) {
    asm volatile(
        "mma.sync.aligned.m16n8k16.row.col.f32.bf16.bf16.f32 "
        "{%0,%1,%2,%3}, {%4,%5,%6,%7}, {%8,%9}, {%0,%1,%2,%3};"
        : "+f"(d[0]), "+f"(d[1]), "+f"(d[2]), "+f"(d[3])
        : "r"(a[0]), "r"(a[1]), "r"(a[2]), "r"(a[3]), "r"(b[0]), "r"(b[1]));
}

// ============================================================================
// tanh-GEMM stage: dest = tanh( A[32xK] @ B^T + bias ); B [256n x K] stride
// B_STR; warp w owns n-cols [32w, 32w+32).
// ============================================================================
template <int KSTEPS, int B_STR>
static __device__ __forceinline__ void gemm_tanh(
    char* smem, uint32_t sb,
    uint32_t a_off, uint32_t a_str,
    uint32_t b_off, uint32_t dest_off, const float* __restrict__ bias,
    int wid, int lane)
{
    const int nb = wid * 32;
    float acc[2][4][4];
    #pragma unroll
    for (int i = 0; i < 2; i++)
        #pragma unroll
        for (int j = 0; j < 4; j++)
            #pragma unroll
            for (int c = 0; c < 4; c++) acc[i][j][c] = 0.f;

    const uint32_t a_base = sb + a_off + (uint32_t)(lane & 15) * a_str
                          + (uint32_t)(lane >> 4) * 16u;
    const uint32_t q = (uint32_t)(lane >> 3), r = (uint32_t)(lane & 7);
    const uint32_t b_base = sb + b_off
                          + (uint32_t)(nb + (int)((q >> 1) * 8) + (int)r) * (uint32_t)B_STR
                          + (q & 1) * 16u;

    #pragma unroll
    for (int ks = 0; ks < KSTEPS; ks++) {
        const uint32_t kb = (uint32_t)ks * 32u;
        uint32_t a0[4], a1[4], b01[4], b23[4];
        ldm_x4(a0, a_base + kb);
        ldm_x4(a1, a_base + 16u * a_str + kb);
        ldm_x4(b01, b_base + kb);
        ldm_x4(b23, b_base + 16u * (uint32_t)B_STR + kb);
        mma_bf16(acc[0][0], a0, b01 + 0);
        mma_bf16(acc[0][1], a0, b01 + 2);
        mma_bf16(acc[0][2], a0, b23 + 0);
        mma_bf16(acc[0][3], a0, b23 + 2);
        mma_bf16(acc[1][0], a1, b01 + 0);
        mma_bf16(acc[1][1], a1, b01 + 2);
        mma_bf16(acc[1][2], a1, b23 + 0);
        mma_bf16(acc[1][3], a1, b23 + 2);
    }

    #pragma unroll
    for (int mt = 0; mt < 2; mt++) {
        const int row = mt * 16 + (lane >> 2);
        #pragma unroll
        for (int nt = 0; nt < 4; nt++) {
            const int col = nb + nt * 8 + 2 * (lane & 3);
            const float bb0 = bias[col], bb1 = bias[col + 1];
            float v0 = fast_tanh(acc[mt][nt][0] + bb0);
            float v1 = fast_tanh(acc[mt][nt][1] + bb1);
            float v2 = fast_tanh(acc[mt][nt][2] + bb0);
            float v3 = fast_tanh(acc[mt][nt][3] + bb1);
            *reinterpret_cast<uint32_t*>(smem + dest_off + (uint32_t)row * H_STR
                                         + (uint32_t)col * 2u) = pack_bf16x2(v0, v1);
            *reinterpret_cast<uint32_t*>(smem + dest_off + (uint32_t)(row + 8) * H_STR
                                         + (uint32_t)col * 2u) = pack_bf16x2(v2, v3);
        }
    }
}

// ============================================================================
// Kernel
// ============================================================================
__global__ void __launch_bounds__(NTHREADS, 1)
neural_ode_kernel(const float* __restrict__ x0, const float* __restrict__ W1,
                  const float* __restrict__ b1, const float* __restrict__ W2,
                  const float* __restrict__ b2, const float* __restrict__ W3,
                  const float* __restrict__ b3, const float* __restrict__ dts,
                  float* __restrict__ out, int T)
{
    extern __shared__ char smem[];
    const uint32_t sb = smem_u32(smem);
    const int tid = threadIdx.x;
    const int wid = tid >> 5;
    const int lane = tid & 31;

    // ---- one-time weight staging (bf16, transposed, padded) ----
    for (int i = tid; i < STATE * HID; i += NTHREADS) {          // W1 [64k][256n]
        int k = i >> 8, n = i & 255;
        *reinterpret_cast<__nv_bfloat16*>(smem + W1_OFF + (uint32_t)n * W1_STR
                                          + (uint32_t)k * 2u) = __float2bfloat16(W1[i]);
    }
    for (int i = tid; i < HID * HID; i += NTHREADS) {            // W2 [256k][256n]
        int k = i >> 8, n = i & 255;
        *reinterpret_cast<__nv_bfloat16*>(smem + W2_OFF + (uint32_t)n * W2_STR
                                          + (uint32_t)k * 2u) = __float2bfloat16(W2[i]);
    }
    for (int i = tid; i < HID * STATE; i += NTHREADS) {          // W3 [256k][64n] -> H1 region (transient)
        int k = i >> 6, n = i & 63;
        *reinterpret_cast<__nv_bfloat16*>(smem + H1_OFF + (uint32_t)n * W3_STR
                                          + (uint32_t)k * 2u) = __float2bfloat16(W3[i]);
    }
    float* b1s = reinterpret_cast<float*>(smem + B1_OFF);
    float* b2s = reinterpret_cast<float*>(smem + B2_OFF);
    float* b3s = reinterpret_cast<float*>(smem + B3_OFF);
    for (int i = tid; i < HID; i += NTHREADS) { b1s[i] = b1[i]; b2s[i] = b2[i]; }
    for (int i = tid; i < STATE; i += NTHREADS) b3s[i] = b3[i];
    __syncthreads();

    // ---- preload W3 B-fragments (loop-invariant) into 32 regs ----
    // warp w owns n-tile w (cols 8w..8w+8); kstep ks uses b3r[(ks>>1)*4 + (ks&1)*2]
    uint32_t b3r[32];
    {
        const uint32_t q = (uint32_t)(lane >> 3), r = (uint32_t)(lane & 7);
        const uint32_t b_base = sb + H1_OFF + (uint32_t)(wid * 8 + (int)r) * W3_STR
                              + q * 16u;
        #pragma unroll
        for (int kk = 0; kk < 8; kk++)
            ldm_x4(b3r + 4 * kk, b_base + (uint32_t)kk * 64u);
    }

    const float dtdt = dts[0] * 0.01f;
    const int nsteps = T - 1;
    const int gb = blockIdx.x * MROWS;           // CTA's first batch row
    const int colb = wid * 8 + 2 * (lane & 3);   // this thread's n-col pair base

    // ---- x state in D-fragment layout: xr[mt][c]; rows mt*16 + (c>>1)*8 + lane>>2
    float xr[2][4];
    {
        #pragma unroll
        for (int mt = 0; mt < 2; mt++)
            #pragma unroll
            for (int half = 0; half < 2; half++) {
                const int row = mt * 16 + half * 8 + (lane >> 2);
                const float2 v = *reinterpret_cast<const float2*>(
                    x0 + (size_t)(gb + row) * STATE + colb);
                xr[mt][2 * half] = v.x;
                xr[mt][2 * half + 1] = v.y;
                *reinterpret_cast<float2*>(
                    out + (size_t)(gb + row) * T * STATE + colb) = v;   // traj t=0
                *reinterpret_cast<uint32_t*>(smem + XB_OFF + (uint32_t)row * XB_STR
                    + (uint32_t)colb * 2u) = pack_bf16x2(v.x, v.y);
            }
    }
    __syncthreads();   // XB ready; W3 preload done before H1 gets overwritten

    for (int s = 0; s < nsteps; s++) {
        // stage 1: H1 = tanh(X @ W1 + b1)
        gemm_tanh<4, W1_STR>(smem, sb, XB_OFF, XB_STR, W1_OFF, H1_OFF, b1s, wid, lane);
        __syncthreads();
        // stage 2: H2 = tanh(H1 @ W2 + b2)
        gemm_tanh<16, W2_STR>(smem, sb, H1_OFF, H_STR, W2_OFF, H2_OFF, b2s, wid, lane);
        __syncthreads();

        // stage 3: F = H2 @ W3 (B in regs) + Euler + traj + next XB, all in frags
        {
            float f3[2][4];
            #pragma unroll
            for (int i = 0; i < 2; i++)
                #pragma unroll
                for (int c = 0; c < 4; c++) f3[i][c] = 0.f;

            const uint32_t a_base = sb + H2_OFF + (uint32_t)(lane & 15) * H_STR
                                  + (uint32_t)(lane >> 4) * 16u;
            #pragma unroll
            for (int ks = 0; ks < 16; ks++) {
                const uint32_t kb = (uint32_t)ks * 32u;
                uint32_t a0[4], a1[4];
                ldm_x4(a0, a_base + kb);
                ldm_x4(a1, a_base + 16u * H_STR + kb);
                const uint32_t* bp = b3r + (ks >> 1) * 4 + (ks & 1) * 2;
                mma_bf16(f3[0], a0, bp);
                mma_bf16(f3[1], a1, bp);
            }

            const float bb0 = b3s[colb], bb1 = b3s[colb + 1];
            #pragma unroll
            for (int mt = 0; mt < 2; mt++) {
                const int row0 = mt * 16 + (lane >> 2);
                xr[mt][0] = fmaf(f3[mt][0] + bb0, dtdt, xr[mt][0]);
                xr[mt][1] = fmaf(f3[mt][1] + bb1, dtdt, xr[mt][1]);
                xr[mt][2] = fmaf(f3[mt][2] + bb0, dtdt, xr[mt][2]);
                xr[mt][3] = fmaf(f3[mt][3] + bb1, dtdt, xr[mt][3]);

                *reinterpret_cast<float2*>(
                    out + ((size_t)(gb + row0) * T + (size_t)(s + 1)) * STATE + colb)
                    = make_float2(xr[mt][0], xr[mt][1]);
                *reinterpret_cast<float2*>(
                    out + ((size_t)(gb + row0 + 8) * T + (size_t)(s + 1)) * STATE + colb)
                    = make_float2(xr[mt][2], xr[mt][3]);

                *reinterpret_cast<uint32_t*>(smem + XB_OFF + (uint32_t)row0 * XB_STR
                    + (uint32_t)colb * 2u) = pack_bf16x2(xr[mt][0], xr[mt][1]);
                *reinterpret_cast<uint32_t*>(smem + XB_OFF + (uint32_t)(row0 + 8) * XB_STR
                    + (uint32_t)colb * 2u) = pack_bf16x2(xr[mt][2], xr[mt][3]);
            }
        }
        __syncthreads();
    }
}

// ============================================================================
// Launch
// ============================================================================
extern "C" void kernel_launch(void* const* d_in, const int* in_sizes, int n_in,
                              void* d_out, int out_size) {
    const float* x0  = (const float*)d_in[0];
    const float* W1  = (const float*)d_in[1];
    const float* b1  = (const float*)d_in[2];
    const float* W2  = (const float*)d_in[3];
    const float* b2  = (const float*)d_in[4];
    const float* W3  = (const float*)d_in[5];
    const float* b3  = (const float*)d_in[6];
    const float* dts = (const float*)d_in[7];
    float* out = (float*)d_out;

    const int T = out_size / (BATCHN * STATE);   // steps + 1

    cudaFuncSetAttribute(neural_ode_kernel,
                         cudaFuncAttributeMaxDynamicSharedMemorySize, SMEM_BYTES);
    neural_ode_kernel<<<NCTAS, NTHREADS, SMEM_BYTES>>>(
        x0, W1, b1, W2, b2, W3, b3, dts, out, T);
}

// round 9
// speedup vs baseline: 1.3181x; 1.1861x over previous
#include <cuda_runtime.h>
#include <cuda_bf16.h>
#include <cstdint>

// ============================================================================
// NeuralODE persistent mma.sync kernel, round 8 (= round-5 design, addr fix).
// 128 CTAs x 32 rows. Per step:
//   stage1: H1 = tanh(X@W1+b1)        (W1 B-frags in registers)
//   stage2: acc2 = H1@W2              (B2 prefetched across barrier)
//   stage3: fused — tanh(acc2+b2) packed straight into A-fragments,
//           partial F = H2_w @ W3_slice from registers (W3 B-frags in regs),
//           bf16 partials reduced 8-way in smem (generic-pointer accesses!).
//   Euler update + trajectory from fragment-resident fp32 state.
// 3 __syncthreads per step. No H2 buffer, no stage-3 ldmatrix.
// ============================================================================

#define STATE     64
#define HID       256
#define BATCHN    4096
#define MROWS     32
#define NCTAS     (BATCHN / MROWS)   // 128
#define NTHREADS  256

// ---- smem strides; (stride/16) odd -> ldmatrix conflict-free ----
#define W2_STR 528
#define W1_STR 144
#define W3_STR 528
#define XB_STR 144
#define H_STR  528
#define RROW_STR 144      // reduction row stride bytes
#define RW_STR  4608      // per-warp partial block: 32 rows x 144

#define W2_OFF 0u          // 135168
#define XB_OFF 135168u     //   4608 -> 139776
#define H1_OFF 139776u     //  16896 -> 156672   (also transient W1/W3 staging)
#define RED_OFF 156672u    //  36864 -> 193536
#define B1S_OFF 193536u
#define B2S_OFF 194560u
#define B3S_OFF 195584u
#define SMEM_BYTES 195840u

// ============================================================================
// helpers
// ============================================================================
static __device__ __forceinline__ uint32_t smem_u32(const void* p) {
    uint32_t a;
    asm("{ .reg .u64 t; cvta.to.shared.u64 t, %1; cvt.u32.u64 %0, t; }"
        : "=r"(a) : "l"(p));
    return a;
}

static __device__ __forceinline__ float fast_tanh(float x) {
    float y;
    asm("tanh.approx.f32 %0, %1;" : "=f"(y) : "f"(x));
    return y;
}

static __device__ __forceinline__ uint32_t pack_bf16x2(float lo, float hi) {
    uint32_t p;
    asm("cvt.rn.bf16x2.f32 %0, %1, %2;" : "=r"(p) : "f"(hi), "f"(lo));
    return p;
}

static __device__ __forceinline__ float bf16lo(uint32_t u) {
    return __uint_as_float(u << 16);
}
static __device__ __forceinline__ float bf16hi(uint32_t u) {
    return __uint_as_float(u & 0xFFFF0000u);
}

static __device__ __forceinline__ void ldm_x4(uint32_t* r, uint32_t addr) {
    asm volatile("ldmatrix.sync.aligned.m8n8.x4.shared.b16 {%0,%1,%2,%3}, [%4];"
                 : "=r"(r[0]), "=r"(r[1]), "=r"(r[2]), "=r"(r[3]) : "r"(addr));
}

static __device__ __forceinline__ void mma_bf16(float* d, const uint32_t* a,
                                                const uint32_t* b) {
    asm volatile(
        "mma.sync.aligned.m16n8k16.row.col.f32.bf16.bf16.f32 "
        "{%0,%1,%2,%3}, {%4,%5,%6,%7}, {%8,%9}, {%0,%1,%2,%3};"
        : "+f"(d[0]), "+f"(d[1]), "+f"(d[2]), "+f"(d[3])
        : "r"(a[0]), "r"(a[1]), "r"(a[2]), "r"(a[3]), "r"(b[0]), "r"(b[1]));
}

// ============================================================================
// Kernel
// ============================================================================
__global__ void __launch_bounds__(NTHREADS, 1)
neural_ode_kernel(const float* __restrict__ x0, const float* __restrict__ W1,
                  const float* __restrict__ b1, const float* __restrict__ W2,
                  const float* __restrict__ b2, const float* __restrict__ W3,
                  const float* __restrict__ b3, const float* __restrict__ dts,
                  float* __restrict__ out, int T)
{
    extern __shared__ char smem[];
    const uint32_t sb = smem_u32(smem);
    const int tid = threadIdx.x;
    const int wid = tid >> 5;
    const int lane = tid & 31;
    const int nb = wid * 32;
    const uint32_t q = (uint32_t)(lane >> 3), r = (uint32_t)(lane & 7);

    // ---- stage W2 (permanent) + W1 (transient at H1_OFF) + biases ----
    for (int i = tid; i < HID * HID; i += NTHREADS) {            // W2 [256k][256n]
        int k = i >> 8, n = i & 255;
        *reinterpret_cast<__nv_bfloat16*>(smem + W2_OFF + (uint32_t)n * W2_STR
                                          + (uint32_t)k * 2u) = __float2bfloat16(W2[i]);
    }
    for (int i = tid; i < STATE * HID; i += NTHREADS) {          // W1 [64k][256n]
        int k = i >> 8, n = i & 255;
        *reinterpret_cast<__nv_bfloat16*>(smem + H1_OFF + (uint32_t)n * W1_STR
                                          + (uint32_t)k * 2u) = __float2bfloat16(W1[i]);
    }
    float* b1s = reinterpret_cast<float*>(smem + B1S_OFF);
    float* b2s = reinterpret_cast<float*>(smem + B2S_OFF);
    float* b3s = reinterpret_cast<float*>(smem + B3S_OFF);
    for (int i = tid; i < HID; i += NTHREADS) { b1s[i] = b1[i]; b2s[i] = b2[i]; }
    for (int i = tid; i < STATE; i += NTHREADS) b3s[i] = b3[i];
    __syncthreads();

    // ---- preload W1 B-fragments: warp w, n-cols 32w..32w+32, all K=64 ----
    uint32_t b1r[32];   // [ks*8 + {b01[0..3], b23[0..3]}]
    {
        const uint32_t bb = sb + H1_OFF
                          + (uint32_t)(nb + (int)((q >> 1) * 8) + (int)r) * W1_STR
                          + (q & 1) * 16u;
        #pragma unroll
        for (int ks = 0; ks < 4; ks++) {
            ldm_x4(b1r + ks * 8,     bb + (uint32_t)ks * 32u);
            ldm_x4(b1r + ks * 8 + 4, bb + 16u * W1_STR + (uint32_t)ks * 32u);
        }
    }
    __syncthreads();

    // ---- stage W3^T [64 n3][256 k] transient at H1_OFF; init x/traj/XB ----
    for (int i = tid; i < HID * STATE; i += NTHREADS) {
        int k = i >> 6, n = i & 63;
        *reinterpret_cast<__nv_bfloat16*>(smem + H1_OFF + (uint32_t)n * W3_STR
                                          + (uint32_t)k * 2u) = __float2bfloat16(W3[i]);
    }

    const float dtdt = dts[0] * 0.01f;
    const int nsteps = T - 1;
    const int gb = blockIdx.x * MROWS;
    const int colb = wid * 8 + 2 * (lane & 3);

    float xr[2][4];   // D-fragment-resident fp32 state
    #pragma unroll
    for (int mt = 0; mt < 2; mt++)
        #pragma unroll
        for (int half = 0; half < 2; half++) {
            const int row = mt * 16 + half * 8 + (lane >> 2);
            const float2 v = *reinterpret_cast<const float2*>(
                x0 + (size_t)(gb + row) * STATE + colb);
            xr[mt][2 * half] = v.x;
            xr[mt][2 * half + 1] = v.y;
            *reinterpret_cast<float2*>(
                out + (size_t)(gb + row) * T * STATE + colb) = v;
            *reinterpret_cast<uint32_t*>(smem + XB_OFF + (uint32_t)row * XB_STR
                + (uint32_t)colb * 2u) = pack_bf16x2(v.x, v.y);
        }
    __syncthreads();

    // ---- preload W3 B-fragments: warp w's k-slice [32w,32w+32), all 64 n3 ----
    uint32_t b3r[32];   // [nt3*4 + {kc0: 0,1 | kc1: 2,3}]
    {
        const uint32_t bb = sb + H1_OFF + r * W3_STR + (uint32_t)(wid * 64) + q * 16u;
        #pragma unroll
        for (int nt3 = 0; nt3 < 8; nt3++)
            ldm_x4(b3r + nt3 * 4, bb + (uint32_t)(nt3 * 8) * W3_STR);
    }
    __syncthreads();

    const uint32_t b2base = sb + W2_OFF
                          + (uint32_t)(nb + (int)((q >> 1) * 8) + (int)r) * W2_STR
                          + (q & 1) * 16u;
    const float bb3_0 = b3s[colb], bb3_1 = b3s[colb + 1];

    for (int s = 0; s < nsteps; s++) {
        // ================= stage 1: H1 = tanh(X@W1+b1), B in regs ==========
        {
            float acc[2][4][4];
            #pragma unroll
            for (int i = 0; i < 2; i++)
                #pragma unroll
                for (int j = 0; j < 4; j++)
                    #pragma unroll
                    for (int c = 0; c < 4; c++) acc[i][j][c] = 0.f;

            const uint32_t a_base = sb + XB_OFF + (uint32_t)(lane & 15) * XB_STR
                                  + (uint32_t)(lane >> 4) * 16u;
            #pragma unroll
            for (int ks = 0; ks < 4; ks++) {
                uint32_t a0[4], a1[4];
                ldm_x4(a0, a_base + (uint32_t)ks * 32u);
                ldm_x4(a1, a_base + 16u * XB_STR + (uint32_t)ks * 32u);
                const uint32_t* bk = b1r + ks * 8;
                mma_bf16(acc[0][0], a0, bk + 0);
                mma_bf16(acc[0][1], a0, bk + 2);
                mma_bf16(acc[0][2], a0, bk + 4);
                mma_bf16(acc[0][3], a0, bk + 6);
                mma_bf16(acc[1][0], a1, bk + 0);
                mma_bf16(acc[1][1], a1, bk + 2);
                mma_bf16(acc[1][2], a1, bk + 4);
                mma_bf16(acc[1][3], a1, bk + 6);
            }
            #pragma unroll
            for (int mt = 0; mt < 2; mt++) {
                const int row = mt * 16 + (lane >> 2);
                #pragma unroll
                for (int nt = 0; nt < 4; nt++) {
                    const int col = nb + nt * 8 + 2 * (lane & 3);
                    const float c0 = b1s[col], c1 = b1s[col + 1];
                    float v0 = fast_tanh(acc[mt][nt][0] + c0);
                    float v1 = fast_tanh(acc[mt][nt][1] + c1);
                    float v2 = fast_tanh(acc[mt][nt][2] + c0);
                    float v3 = fast_tanh(acc[mt][nt][3] + c1);
                    *reinterpret_cast<uint32_t*>(smem + H1_OFF + (uint32_t)row * H_STR
                        + (uint32_t)col * 2u) = pack_bf16x2(v0, v1);
                    *reinterpret_cast<uint32_t*>(smem + H1_OFF + (uint32_t)(row + 8) * H_STR
                        + (uint32_t)col * 2u) = pack_bf16x2(v2, v3);
                }
            }
        }

        // prefetch B2 for ks=0 BEFORE the barrier (W2 is static)
        uint32_t bcur[8];
        ldm_x4(bcur,     b2base);
        ldm_x4(bcur + 4, b2base + 16u * W2_STR);
        __syncthreads();                              // H1 visible

        // ================= stage 2: acc2 = H1 @ W2 (K=256) =================
        float acc2[2][4][4];
        #pragma unroll
        for (int i = 0; i < 2; i++)
            #pragma unroll
            for (int j = 0; j < 4; j++)
                #pragma unroll
                for (int c = 0; c < 4; c++) acc2[i][j][c] = 0.f;
        {
            const uint32_t a_base = sb + H1_OFF + (uint32_t)(lane & 15) * H_STR
                                  + (uint32_t)(lane >> 4) * 16u;
            #pragma unroll
            for (int ks = 0; ks < 16; ks++) {
                uint32_t a0[4], a1[4], bn[8];
                ldm_x4(a0, a_base + (uint32_t)ks * 32u);
                ldm_x4(a1, a_base + 16u * H_STR + (uint32_t)ks * 32u);
                if (ks < 15) {
                    ldm_x4(bn,     b2base + (uint32_t)(ks + 1) * 32u);
                    ldm_x4(bn + 4, b2base + 16u * W2_STR + (uint32_t)(ks + 1) * 32u);
                }
                mma_bf16(acc2[0][0], a0, bcur + 0);
                mma_bf16(acc2[0][1], a0, bcur + 2);
                mma_bf16(acc2[0][2], a0, bcur + 4);
                mma_bf16(acc2[0][3], a0, bcur + 6);
                mma_bf16(acc2[1][0], a1, bcur + 0);
                mma_bf16(acc2[1][1], a1, bcur + 2);
                mma_bf16(acc2[1][2], a1, bcur + 4);
                mma_bf16(acc2[1][3], a1, bcur + 6);
                if (ks < 15) {
                    #pragma unroll
                    for (int t = 0; t < 8; t++) bcur[t] = bn[t];
                }
            }
        }

        // ======= fused stage 3: tanh -> A-frags -> partial F from regs =====
        {
            uint32_t p[2][4][2];   // tanh(H2) packed; [mt][nt][half-row]
            #pragma unroll
            for (int mt = 0; mt < 2; mt++)
                #pragma unroll
                for (int nt = 0; nt < 4; nt++) {
                    const int col = nb + nt * 8 + 2 * (lane & 3);
                    const float c0 = b2s[col], c1 = b2s[col + 1];
                    float v0 = fast_tanh(acc2[mt][nt][0] + c0);
                    float v1 = fast_tanh(acc2[mt][nt][1] + c1);
                    float v2 = fast_tanh(acc2[mt][nt][2] + c0);
                    float v3 = fast_tanh(acc2[mt][nt][3] + c1);
                    p[mt][nt][0] = pack_bf16x2(v0, v1);
                    p[mt][nt][1] = pack_bf16x2(v2, v3);
                }

            float f3[2][8][4];
            #pragma unroll
            for (int mt = 0; mt < 2; mt++)
                #pragma unroll
                for (int nt3 = 0; nt3 < 8; nt3++)
                    #pragma unroll
                    for (int c = 0; c < 4; c++) f3[mt][nt3][c] = 0.f;

            #pragma unroll
            for (int mt = 0; mt < 2; mt++)
                #pragma unroll
                for (int kc = 0; kc < 2; kc++) {
                    uint32_t af[4] = { p[mt][2 * kc][0], p[mt][2 * kc][1],
                                       p[mt][2 * kc + 1][0], p[mt][2 * kc + 1][1] };
                    #pragma unroll
                    for (int nt3 = 0; nt3 < 8; nt3++)
                        mma_bf16(f3[mt][nt3], af, b3r + nt3 * 4 + kc * 2);
                }

            // write bf16 partials via GENERIC pointers off `smem` (bug fix)
            const uint32_t rbo = RED_OFF + (uint32_t)wid * RW_STR
                               + (uint32_t)(2 * (lane & 3)) * 2u
                               + (uint32_t)(lane >> 2) * RROW_STR;
            #pragma unroll
            for (int mt = 0; mt < 2; mt++)
                #pragma unroll
                for (int nt3 = 0; nt3 < 8; nt3++) {
                    const uint32_t cb = (uint32_t)(nt3 * 8) * 2u
                                      + (uint32_t)(mt * 16) * RROW_STR;
                    *reinterpret_cast<uint32_t*>(smem + rbo + cb)
                        = pack_bf16x2(f3[mt][nt3][0], f3[mt][nt3][1]);
                    *reinterpret_cast<uint32_t*>(smem + rbo + cb + 8u * RROW_STR)
                        = pack_bf16x2(f3[mt][nt3][2], f3[mt][nt3][3]);
                }
        }
        __syncthreads();                              // partials ready

        // ====== reduce 8 partials + Euler + trajectory + next XB ===========
        #pragma unroll
        for (int mt = 0; mt < 2; mt++)
            #pragma unroll
            for (int half = 0; half < 2; half++) {
                const int row = mt * 16 + half * 8 + (lane >> 2);
                const uint32_t a0 = RED_OFF + (uint32_t)row * RROW_STR
                                  + (uint32_t)colb * 2u;
                float s0 = 0.f, s1 = 0.f;
                #pragma unroll
                for (int w2 = 0; w2 < 8; w2++) {
                    uint32_t u = *reinterpret_cast<const uint32_t*>(
                        smem + a0 + (uint32_t)w2 * RW_STR);
                    s0 += bf16lo(u);
                    s1 += bf16hi(u);
                }
                float xa = fmaf(s0 + bb3_0, dtdt, xr[mt][2 * half]);
                float xb = fmaf(s1 + bb3_1, dtdt, xr[mt][2 * half + 1]);
                xr[mt][2 * half] = xa;
                xr[mt][2 * half + 1] = xb;
                *reinterpret_cast<float2*>(
                    out + ((size_t)(gb + row) * T + (size_t)(s + 1)) * STATE + colb)
                    = make_float2(xa, xb);
                *reinterpret_cast<uint32_t*>(smem + XB_OFF + (uint32_t)row * XB_STR
                    + (uint32_t)colb * 2u) = pack_bf16x2(xa, xb);
            }
        __syncthreads();                              // XB ready, RED consumed
    }
}

// ============================================================================
// Launch
// ============================================================================
extern "C" void kernel_launch(void* const* d_in, const int* in_sizes, int n_in,
                              void* d_out, int out_size) {
    const float* x0  = (const float*)d_in[0];
    const float* W1  = (const float*)d_in[1];
    const float* b1  = (const float*)d_in[2];
    const float* W2  = (const float*)d_in[3];
    const float* b2  = (const float*)d_in[4];
    const float* W3  = (const float*)d_in[5];
    const float* b3  = (const float*)d_in[6];
    const float* dts = (const float*)d_in[7];
    float* out = (float*)d_out;

    const int T = out_size / (BATCHN * STATE);   // steps + 1

    cudaFuncSetAttribute(neural_ode_kernel,
                         cudaFuncAttributeMaxDynamicSharedMemorySize, SMEM_BYTES);
    neural_ode_kernel<<<NCTAS, NTHREADS, SMEM_BYTES>>>(
        x0, W1, b1, W2, b2, W3, b3, dts, out, T);
}

// round 10
// speedup vs baseline: 1.3254x; 1.0055x over previous
#include <cuda_runtime.h>
#include <cuda_bf16.h>
#include <cstdint>

// ============================================================================
// NeuralODE persistent mma.sync kernel, round 9 (R8 design + deep pipelining).
// 128 CTAs x 32 rows. Per step:
//   stage1: H1 = tanh(X@W1+b1)   (W1 B-frags in regs; A ldmatrix batched)
//   stage2: acc2 = H1@W2         (A and B fragments double-buffered)
//   stage3: fused tanh->A-frags, partial F = H2_w @ W3_slice from regs,
//           bf16 partials reduced 8-way in smem (loads gathered first).
//   Euler update + trajectory from fragment-resident fp32 state.
// 3 __syncthreads per step.
// ============================================================================

#define STATE     64
#define HID       256
#define BATCHN    4096
#define MROWS     32
#define NCTAS     (BATCHN / MROWS)   // 128
#define NTHREADS  256

// ---- smem strides; (stride/16) odd -> ldmatrix conflict-free ----
#define W2_STR 528
#define W1_STR 144
#define W3_STR 528
#define XB_STR 144
#define H_STR  528
#define RROW_STR 144      // reduction row stride bytes
#define RW_STR  4608      // per-warp partial block: 32 rows x 144

#define W2_OFF 0u          // 135168
#define XB_OFF 135168u     //   4608 -> 139776
#define H1_OFF 139776u     //  16896 -> 156672   (also transient W1/W3 staging)
#define RED_OFF 156672u    //  36864 -> 193536
#define B1S_OFF 193536u
#define B2S_OFF 194560u
#define B3S_OFF 195584u
#define SMEM_BYTES 195840u

// ============================================================================
// helpers
// ============================================================================
static __device__ __forceinline__ uint32_t smem_u32(const void* p) {
    uint32_t a;
    asm("{ .reg .u64 t; cvta.to.shared.u64 t, %1; cvt.u32.u64 %0, t; }"
        : "=r"(a) : "l"(p));
    return a;
}

static __device__ __forceinline__ float fast_tanh(float x) {
    float y;
    asm("tanh.approx.f32 %0, %1;" : "=f"(y) : "f"(x));
    return y;
}

static __device__ __forceinline__ uint32_t pack_bf16x2(float lo, float hi) {
    uint32_t p;
    asm("cvt.rn.bf16x2.f32 %0, %1, %2;" : "=r"(p) : "f"(hi), "f"(lo));
    return p;
}

static __device__ __forceinline__ float bf16lo(uint32_t u) {
    return __uint_as_float(u << 16);
}
static __device__ __forceinline__ float bf16hi(uint32_t u) {
    return __uint_as_float(u & 0xFFFF0000u);
}

static __device__ __forceinline__ void ldm_x4(uint32_t* r, uint32_t addr) {
    asm volatile("ldmatrix.sync.aligned.m8n8.x4.shared.b16 {%0,%1,%2,%3}, [%4];"
                 : "=r"(r[0]), "=r"(r[1]), "=r"(r[2]), "=r"(r[3]) : "r"(addr));
}

static __device__ __forceinline__ void mma_bf16(float* d, const uint32_t* a,
                                                const uint32_t* b) {
    asm volatile(
        "mma.sync.aligned.m16n8k16.row.col.f32.bf16.bf16.f32 "
        "{%0,%1,%2,%3}, {%4,%5,%6,%7}, {%8,%9}, {%0,%1,%2,%3};"
        : "+f"(d[0]), "+f"(d[1]), "+f"(d[2]), "+f"(d[3])
        : "r"(a[0]), "r"(a[1]), "r"(a[2]), "r"(a[3]), "r"(b[0]), "r"(b[1]));
}

// ============================================================================
// Kernel
// ============================================================================
__global__ void __launch_bounds__(NTHREADS, 1)
neural_ode_kernel(const float* __restrict__ x0, const float* __restrict__ W1,
                  const float* __restrict__ b1, const float* __restrict__ W2,
                  const float* __restrict__ b2, const float* __restrict__ W3,
                  const float* __restrict__ b3, const float* __restrict__ dts,
                  float* __restrict__ out, int T)
{
    extern __shared__ char smem[];
    const uint32_t sb = smem_u32(smem);
    const int tid = threadIdx.x;
    const int wid = tid >> 5;
    const int lane = tid & 31;
    const int nb = wid * 32;
    const uint32_t q = (uint32_t)(lane >> 3), r = (uint32_t)(lane & 7);

    // ---- stage W2 (permanent) + W1 (transient at H1_OFF) + biases ----
    for (int i = tid; i < HID * HID; i += NTHREADS) {            // W2 [256k][256n]
        int k = i >> 8, n = i & 255;
        *reinterpret_cast<__nv_bfloat16*>(smem + W2_OFF + (uint32_t)n * W2_STR
                                          + (uint32_t)k * 2u) = __float2bfloat16(W2[i]);
    }
    for (int i = tid; i < STATE * HID; i += NTHREADS) {          // W1 [64k][256n]
        int k = i >> 8, n = i & 255;
        *reinterpret_cast<__nv_bfloat16*>(smem + H1_OFF + (uint32_t)n * W1_STR
                                          + (uint32_t)k * 2u) = __float2bfloat16(W1[i]);
    }
    float* b1s = reinterpret_cast<float*>(smem + B1S_OFF);
    float* b2s = reinterpret_cast<float*>(smem + B2S_OFF);
    float* b3s = reinterpret_cast<float*>(smem + B3S_OFF);
    for (int i = tid; i < HID; i += NTHREADS) { b1s[i] = b1[i]; b2s[i] = b2[i]; }
    for (int i = tid; i < STATE; i += NTHREADS) b3s[i] = b3[i];
    __syncthreads();

    // ---- preload W1 B-fragments: warp w, n-cols 32w..32w+32, all K=64 ----
    uint32_t b1r[32];   // [ks*8 + {b01[0..3], b23[0..3]}]
    {
        const uint32_t bb = sb + H1_OFF
                          + (uint32_t)(nb + (int)((q >> 1) * 8) + (int)r) * W1_STR
                          + (q & 1) * 16u;
        #pragma unroll
        for (int ks = 0; ks < 4; ks++) {
            ldm_x4(b1r + ks * 8,     bb + (uint32_t)ks * 32u);
            ldm_x4(b1r + ks * 8 + 4, bb + 16u * W1_STR + (uint32_t)ks * 32u);
        }
    }
    __syncthreads();

    // ---- stage W3^T [64 n3][256 k] transient at H1_OFF; init x/traj/XB ----
    for (int i = tid; i < HID * STATE; i += NTHREADS) {
        int k = i >> 6, n = i & 63;
        *reinterpret_cast<__nv_bfloat16*>(smem + H1_OFF + (uint32_t)n * W3_STR
                                          + (uint32_t)k * 2u) = __float2bfloat16(W3[i]);
    }

    const float dtdt = dts[0] * 0.01f;
    const int nsteps = T - 1;
    const int gb = blockIdx.x * MROWS;
    const int colb = wid * 8 + 2 * (lane & 3);

    float xr[2][4];   // D-fragment-resident fp32 state
    #pragma unroll
    for (int mt = 0; mt < 2; mt++)
        #pragma unroll
        for (int half = 0; half < 2; half++) {
            const int row = mt * 16 + half * 8 + (lane >> 2);
            const float2 v = *reinterpret_cast<const float2*>(
                x0 + (size_t)(gb + row) * STATE + colb);
            xr[mt][2 * half] = v.x;
            xr[mt][2 * half + 1] = v.y;
            *reinterpret_cast<float2*>(
                out + (size_t)(gb + row) * T * STATE + colb) = v;
            *reinterpret_cast<uint32_t*>(smem + XB_OFF + (uint32_t)row * XB_STR
                + (uint32_t)colb * 2u) = pack_bf16x2(v.x, v.y);
        }
    __syncthreads();

    // ---- preload W3 B-fragments: warp w's k-slice [32w,32w+32), all 64 n3 ----
    uint32_t b3r[32];   // [nt3*4 + {kc0: 0,1 | kc1: 2,3}]
    {
        const uint32_t bb = sb + H1_OFF + r * W3_STR + (uint32_t)(wid * 64) + q * 16u;
        #pragma unroll
        for (int nt3 = 0; nt3 < 8; nt3++)
            ldm_x4(b3r + nt3 * 4, bb + (uint32_t)(nt3 * 8) * W3_STR);
    }
    __syncthreads();

    const uint32_t b2base = sb + W2_OFF
                          + (uint32_t)(nb + (int)((q >> 1) * 8) + (int)r) * W2_STR
                          + (q & 1) * 16u;
    const float bb3_0 = b3s[colb], bb3_1 = b3s[colb + 1];

    for (int s = 0; s < nsteps; s++) {
        // ====== stage 1: H1 = tanh(X@W1+b1), B in regs, A loads batched =====
        {
            // batch all 8 A-ldmatrix first (MLP=8)
            uint32_t a[8][4];
            const uint32_t a_base = sb + XB_OFF + (uint32_t)(lane & 15) * XB_STR
                                  + (uint32_t)(lane >> 4) * 16u;
            #pragma unroll
            for (int ks = 0; ks < 4; ks++) {
                ldm_x4(a[2 * ks],     a_base + (uint32_t)ks * 32u);
                ldm_x4(a[2 * ks + 1], a_base + 16u * XB_STR + (uint32_t)ks * 32u);
            }

            float acc[2][4][4];
            #pragma unroll
            for (int i = 0; i < 2; i++)
                #pragma unroll
                for (int j = 0; j < 4; j++)
                    #pragma unroll
                    for (int c = 0; c < 4; c++) acc[i][j][c] = 0.f;

            #pragma unroll
            for (int ks = 0; ks < 4; ks++) {
                const uint32_t* bk = b1r + ks * 8;
                mma_bf16(acc[0][0], a[2 * ks], bk + 0);
                mma_bf16(acc[0][1], a[2 * ks], bk + 2);
                mma_bf16(acc[0][2], a[2 * ks], bk + 4);
                mma_bf16(acc[0][3], a[2 * ks], bk + 6);
                mma_bf16(acc[1][0], a[2 * ks + 1], bk + 0);
                mma_bf16(acc[1][1], a[2 * ks + 1], bk + 2);
                mma_bf16(acc[1][2], a[2 * ks + 1], bk + 4);
                mma_bf16(acc[1][3], a[2 * ks + 1], bk + 6);
            }
            #pragma unroll
            for (int mt = 0; mt < 2; mt++) {
                const int row = mt * 16 + (lane >> 2);
                #pragma unroll
                for (int nt = 0; nt < 4; nt++) {
                    const int col = nb + nt * 8 + 2 * (lane & 3);
                    const float c0 = b1s[col], c1 = b1s[col + 1];
                    float v0 = fast_tanh(acc[mt][nt][0] + c0);
                    float v1 = fast_tanh(acc[mt][nt][1] + c1);
                    float v2 = fast_tanh(acc[mt][nt][2] + c0);
                    float v3 = fast_tanh(acc[mt][nt][3] + c1);
                    *reinterpret_cast<uint32_t*>(smem + H1_OFF + (uint32_t)row * H_STR
                        + (uint32_t)col * 2u) = pack_bf16x2(v0, v1);
                    *reinterpret_cast<uint32_t*>(smem + H1_OFF + (uint32_t)(row + 8) * H_STR
                        + (uint32_t)col * 2u) = pack_bf16x2(v2, v3);
                }
            }
        }

        // prefetch B2 for ks=0 BEFORE the barrier (W2 is static)
        uint32_t bcur[8];
        ldm_x4(bcur,     b2base);
        ldm_x4(bcur + 4, b2base + 16u * W2_STR);
        __syncthreads();                              // H1 visible

        // ====== stage 2: acc2 = H1 @ W2 (K=256), A and B double-buffered ====
        float acc2[2][4][4];
        #pragma unroll
        for (int i = 0; i < 2; i++)
            #pragma unroll
            for (int j = 0; j < 4; j++)
                #pragma unroll
                for (int c = 0; c < 4; c++) acc2[i][j][c] = 0.f;
        {
            const uint32_t a_base = sb + H1_OFF + (uint32_t)(lane & 15) * H_STR
                                  + (uint32_t)(lane >> 4) * 16u;
            uint32_t ac[8];                           // current A frags (m0|m1)
            ldm_x4(ac,     a_base);
            ldm_x4(ac + 4, a_base + 16u * H_STR);
            #pragma unroll
            for (int ks = 0; ks < 16; ks++) {
                uint32_t an[8], bn[8];
                if (ks < 15) {                        // issue next-iter loads FIRST
                    ldm_x4(an,     a_base + (uint32_t)(ks + 1) * 32u);
                    ldm_x4(an + 4, a_base + 16u * H_STR + (uint32_t)(ks + 1) * 32u);
                    ldm_x4(bn,     b2base + (uint32_t)(ks + 1) * 32u);
                    ldm_x4(bn + 4, b2base + 16u * W2_STR + (uint32_t)(ks + 1) * 32u);
                }
                mma_bf16(acc2[0][0], ac,     bcur + 0);
                mma_bf16(acc2[0][1], ac,     bcur + 2);
                mma_bf16(acc2[0][2], ac,     bcur + 4);
                mma_bf16(acc2[0][3], ac,     bcur + 6);
                mma_bf16(acc2[1][0], ac + 4, bcur + 0);
                mma_bf16(acc2[1][1], ac + 4, bcur + 2);
                mma_bf16(acc2[1][2], ac + 4, bcur + 4);
                mma_bf16(acc2[1][3], ac + 4, bcur + 6);
                if (ks < 15) {
                    #pragma unroll
                    for (int t = 0; t < 8; t++) { ac[t] = an[t]; bcur[t] = bn[t]; }
                }
            }
        }

        // ======= fused stage 3: tanh -> A-frags -> partial F from regs =====
        {
            uint32_t p[2][4][2];   // tanh(H2) packed; [mt][nt][half-row]
            #pragma unroll
            for (int mt = 0; mt < 2; mt++)
                #pragma unroll
                for (int nt = 0; nt < 4; nt++) {
                    const int col = nb + nt * 8 + 2 * (lane & 3);
                    const float c0 = b2s[col], c1 = b2s[col + 1];
                    float v0 = fast_tanh(acc2[mt][nt][0] + c0);
                    float v1 = fast_tanh(acc2[mt][nt][1] + c1);
                    float v2 = fast_tanh(acc2[mt][nt][2] + c0);
                    float v3 = fast_tanh(acc2[mt][nt][3] + c1);
                    p[mt][nt][0] = pack_bf16x2(v0, v1);
                    p[mt][nt][1] = pack_bf16x2(v2, v3);
                }

            const uint32_t rbo = RED_OFF + (uint32_t)wid * RW_STR
                               + (uint32_t)(2 * (lane & 3)) * 2u
                               + (uint32_t)(lane >> 2) * RROW_STR;

            // mt=0: mma then write (its stores overlap mt=1's mma below)
            #pragma unroll
            for (int mt = 0; mt < 2; mt++) {
                float f3[8][4];
                #pragma unroll
                for (int nt3 = 0; nt3 < 8; nt3++)
                    #pragma unroll
                    for (int c = 0; c < 4; c++) f3[nt3][c] = 0.f;
                #pragma unroll
                for (int kc = 0; kc < 2; kc++) {
                    uint32_t af[4] = { p[mt][2 * kc][0], p[mt][2 * kc][1],
                                       p[mt][2 * kc + 1][0], p[mt][2 * kc + 1][1] };
                    #pragma unroll
                    for (int nt3 = 0; nt3 < 8; nt3++)
                        mma_bf16(f3[nt3], af, b3r + nt3 * 4 + kc * 2);
                }
                #pragma unroll
                for (int nt3 = 0; nt3 < 8; nt3++) {
                    const uint32_t cb = (uint32_t)(nt3 * 8) * 2u
                                      + (uint32_t)(mt * 16) * RROW_STR;
                    *reinterpret_cast<uint32_t*>(smem + rbo + cb)
                        = pack_bf16x2(f3[nt3][0], f3[nt3][1]);
                    *reinterpret_cast<uint32_t*>(smem + rbo + cb + 8u * RROW_STR)
                        = pack_bf16x2(f3[nt3][2], f3[nt3][3]);
                }
            }
        }
        __syncthreads();                              // partials ready

        // ====== reduce 8 partials + Euler + trajectory + next XB ===========
        {
            // gather ALL partial loads first (MLP=32), then arithmetic
            uint32_t u[4][8];
            #pragma unroll
            for (int mt = 0; mt < 2; mt++)
                #pragma unroll
                for (int half = 0; half < 2; half++) {
                    const int row = mt * 16 + half * 8 + (lane >> 2);
                    const uint32_t a0 = RED_OFF + (uint32_t)row * RROW_STR
                                      + (uint32_t)colb * 2u;
                    #pragma unroll
                    for (int w2 = 0; w2 < 8; w2++)
                        u[mt * 2 + half][w2] = *reinterpret_cast<const uint32_t*>(
                            smem + a0 + (uint32_t)w2 * RW_STR);
                }
            #pragma unroll
            for (int mt = 0; mt < 2; mt++)
                #pragma unroll
                for (int half = 0; half < 2; half++) {
                    const int row = mt * 16 + half * 8 + (lane >> 2);
                    const uint32_t* up = u[mt * 2 + half];
                    float s0 = 0.f, s1 = 0.f;
                    #pragma unroll
                    for (int w2 = 0; w2 < 8; w2++) {
                        s0 += bf16lo(up[w2]);
                        s1 += bf16hi(up[w2]);
                    }
                    float xa = fmaf(s0 + bb3_0, dtdt, xr[mt][2 * half]);
                    float xb = fmaf(s1 + bb3_1, dtdt, xr[mt][2 * half + 1]);
                    xr[mt][2 * half] = xa;
                    xr[mt][2 * half + 1] = xb;
                    *reinterpret_cast<uint32_t*>(smem + XB_OFF + (uint32_t)row * XB_STR
                        + (uint32_t)colb * 2u) = pack_bf16x2(xa, xb);
                    *reinterpret_cast<float2*>(
                        out + ((size_t)(gb + row) * T + (size_t)(s + 1)) * STATE + colb)
                        = make_float2(xa, xb);
                }
        }
        __syncthreads();                              // XB ready, RED consumed
    }
}

// ============================================================================
// Launch
// ============================================================================
extern "C" void kernel_launch(void* const* d_in, const int* in_sizes, int n_in,
                              void* d_out, int out_size) {
    const float* x0  = (const float*)d_in[0];
    const float* W1  = (const float*)d_in[1];
    const float* b1  = (const float*)d_in[2];
    const float* W2  = (const float*)d_in[3];
    const float* b2  = (const float*)d_in[4];
    const float* W3  = (const float*)d_in[5];
    const float* b3  = (const float*)d_in[6];
    const float* dts = (const float*)d_in[7];
    float* out = (float*)d_out;

    const int T = out_size / (BATCHN * STATE);   // steps + 1

    cudaFuncSetAttribute(neural_ode_kernel,
                         cudaFuncAttributeMaxDynamicSharedMemorySize, SMEM_BYTES);
    neural_ode_kernel<<<NCTAS, NTHREADS, SMEM_BYTES>>>(
        x0, W1, b1, W2, b2, W3, b3, dts, out, T);
}